// round 12
// baseline (speedup 1.0000x reference)
#include <cuda_runtime.h>

// MaskedMSE: B=16, C=4, H=W=512 — single kernel, MLP-maximized streaming.
// input : d_in[0]  float32 [16, 4, 512, 512]
// target: d_in[1]  float32 [16, 5, 512, 512]  (channel 4 is the {0,1} mask)
// out   : d_out    float32 [1]
//
// 16 batches x 37 blocks = 592 streaming blocks = exactly 4 per SM (148 SMs),
// one perfectly balanced wave. __launch_bounds__(256, 4) gives ptxas a 64-reg
// budget so all 9 independent 128-bit loads of an iteration stay in flight
// (MLP ~9 instead of the reg-starved ~3 at 32 regs).
// Block 592 is a dedicated folder: spins on an acquire-load of a release
// ticket, then folds all partials in FIXED order (atomics only count ->
// deterministic), per_b = cnt>0 ? sse/(C*cnt) : 0, writes mean over B,
// resets the ticket for the next graph replay.

#define HW      262144          // 512*512
#define HW4     65536           // HW / 4 (float4 units)
#define CH      4
#define BATCH   16
#define BPB     37              // streaming blocks per batch
#define TPB     256             // threads per block
#define NSTREAM (BATCH * BPB)   // 592 = 4 * 148

__device__ float2       g_partials[NSTREAM];
__device__ unsigned int g_ticket = 0;

__global__ __launch_bounds__(TPB, 4) void masked_mse_mlp(
    const float* __restrict__ input,
    const float* __restrict__ target,
    float* __restrict__ out)
{
    const int tid  = threadIdx.x;
    const int lane = tid & 31;
    const int wid  = tid >> 5;

    // ---------------- folder block (launched last; work-steals a slot) ----
    if (blockIdx.x == NSTREAM) {
        if (tid == 0) {
            unsigned int v;
            for (;;) {
                asm volatile("ld.acquire.gpu.global.u32 %0, [%1];"
                             : "=r"(v) : "l"(&g_ticket) : "memory");
                if (v >= NSTREAM) break;
                __nanosleep(64);
            }
        }
        __syncthreads();

        // 8 warps; warp w folds batches 2w and 2w+1 (fixed order).
        __shared__ float s_per_b[BATCH];
        #pragma unroll
        for (int i = 0; i < 2; i++) {
            const int b = wid * 2 + i;
            float bs = 0.0f, bc = 0.0f;
            if (lane < BPB) {
                const float2 p = __ldcg(&g_partials[b * BPB + lane]);
                bs = p.x; bc = p.y;
            }
            if (lane + 32 < BPB) {
                const float2 p = __ldcg(&g_partials[b * BPB + lane + 32]);
                bs += p.x; bc += p.y;
            }
            #pragma unroll
            for (int o = 16; o > 0; o >>= 1) {
                bs += __shfl_down_sync(0xFFFFFFFFu, bs, o);
                bc += __shfl_down_sync(0xFFFFFFFFu, bc, o);
            }
            if (lane == 0)
                s_per_b[b] = (bc > 0.0f) ? bs / ((float)CH * bc) : 0.0f;
        }
        __syncthreads();

        if (tid == 0) {
            float total = 0.0f;
            #pragma unroll
            for (int i = 0; i < BATCH; i++) total += s_per_b[i];
            out[0] = total / (float)BATCH;
            g_ticket = 0;   // reset for the next graph replay
        }
        return;
    }

    // ---------------- streaming blocks ----------------
    const int b   = (int)(blockIdx.x) / BPB;   // batch
    const int blk = (int)(blockIdx.x) % BPB;   // sub-block within batch

    const float4* __restrict__ inb = (const float4*)(input  + (size_t)b * CH * HW);
    const float4* __restrict__ tgb = (const float4*)(target + (size_t)b * (CH + 1) * HW);
    const float4* __restrict__ mb  = (const float4*)(target + (size_t)b * (CH + 1) * HW + (size_t)CH * HW);

    float sse = 0.0f;
    float cnt = 0.0f;

    // ceil(65536 / 9472) = 7 iterations max per thread.
    for (int p = blk * TPB + tid; p < HW4; p += BPB * TPB) {
        // Batch ALL loads first — 9 independent LDG.128 in flight.
        const float4 m  = mb[p];
        float4 a0 = inb[0 * HW4 + p];
        float4 a1 = inb[1 * HW4 + p];
        float4 a2 = inb[2 * HW4 + p];
        float4 a3 = inb[3 * HW4 + p];
        float4 t0 = tgb[0 * HW4 + p];
        float4 t1 = tgb[1 * HW4 + p];
        float4 t2 = tgb[2 * HW4 + p];
        float4 t3 = tgb[3 * HW4 + p];

        cnt += m.x + m.y + m.z + m.w;

        float dx, dy, dz, dw;
        dx = a0.x - t0.x; dy = a0.y - t0.y; dz = a0.z - t0.z; dw = a0.w - t0.w;
        sse += m.x * (dx * dx); sse += m.y * (dy * dy);
        sse += m.z * (dz * dz); sse += m.w * (dw * dw);
        dx = a1.x - t1.x; dy = a1.y - t1.y; dz = a1.z - t1.z; dw = a1.w - t1.w;
        sse += m.x * (dx * dx); sse += m.y * (dy * dy);
        sse += m.z * (dz * dz); sse += m.w * (dw * dw);
        dx = a2.x - t2.x; dy = a2.y - t2.y; dz = a2.z - t2.z; dw = a2.w - t2.w;
        sse += m.x * (dx * dx); sse += m.y * (dy * dy);
        sse += m.z * (dz * dz); sse += m.w * (dw * dw);
        dx = a3.x - t3.x; dy = a3.y - t3.y; dz = a3.z - t3.z; dw = a3.w - t3.w;
        sse += m.x * (dx * dx); sse += m.y * (dy * dy);
        sse += m.z * (dz * dz); sse += m.w * (dw * dw);
    }

    // intra-warp reduce
    #pragma unroll
    for (int o = 16; o > 0; o >>= 1) {
        sse += __shfl_down_sync(0xFFFFFFFFu, sse, o);
        cnt += __shfl_down_sync(0xFFFFFFFFu, cnt, o);
    }

    __shared__ float s_sse[TPB / 32];
    __shared__ float s_cnt[TPB / 32];
    if (lane == 0) { s_sse[wid] = sse; s_cnt[wid] = cnt; }
    __syncthreads();

    if (wid != 0) return;

    sse = (lane < TPB / 32) ? s_sse[lane] : 0.0f;
    cnt = (lane < TPB / 32) ? s_cnt[lane] : 0.0f;
    #pragma unroll
    for (int o = 4; o > 0; o >>= 1) {
        sse += __shfl_down_sync(0xFFFFFFFFu, sse, o);
        cnt += __shfl_down_sync(0xFFFFFFFFu, cnt, o);
    }

    if (lane == 0) {
        g_partials[b * BPB + blk] = make_float2(sse, cnt);
        // Release RED: orders the partial store before the count increment,
        // no return trip, no L1 flush.
        asm volatile("red.release.gpu.global.add.u32 [%0], 1;"
                     :: "l"(&g_ticket) : "memory");
    }
}

extern "C" void kernel_launch(void* const* d_in, const int* in_sizes, int n_in,
                              void* d_out, int out_size)
{
    const float* input  = (const float*)d_in[0];
    const float* target = (const float*)d_in[1];
    float*       out    = (float*)d_out;

    masked_mse_mlp<<<NSTREAM + 1, TPB>>>(input, target, out);
}